// round 17
// baseline (speedup 1.0000x reference)
#include <cuda_runtime.h>
#include <cuda_fp16.h>
#include <cstdint>

#define NB 16
#define NS 1024
#define NF 512
#define NH 8
#define NDK 64
#define NHDK 512
#define NROWS (NB*NS)   // 16384

#define QSCALE 0.18033688011112042f   // log2(e)/8, folded into Q at projection
#define LN2F   0.69314718055994531f
#define LOG2EF 1.4426950408889634f
#define MASKL2 (-1442693.6f)          // -999999 * log2(e)

// Scratch (allocation-free rule: __device__ globals), all fp16 (rne-rounded)
__device__ __align__(16) __half g_q[NB*NH*NS*NDK];   // [B,H,S,DK] (pre-scaled by QSCALE)
__device__ __align__(16) __half g_k[NB*NH*NS*NDK];
__device__ __align__(16) __half g_v[NB*NH*NS*NDK];
__device__ __align__(16) __half g_z[NROWS*NHDK];     // [B,S,H*DK]
__device__ __align__(16) __half g_x[NROWS*NF];
__device__ __align__(16) __half g_wqkv[3*NHDK*NF];
__device__ __align__(16) __half g_wo[NF*NHDK];

// ---------------------------------------------------------------------------
// helpers
// ---------------------------------------------------------------------------
__device__ __forceinline__ uint32_t pack_h2(float a, float b) {
    __half2 h = __floats2half2_rn(a, b);   // low = a, high = b
    return *reinterpret_cast<uint32_t*>(&h);
}

__device__ __forceinline__ uint32_t ex2_h2(uint32_t h2) {
    uint32_t y;
    asm("ex2.approx.f16x2 %0, %1;" : "=r"(y) : "r"(h2));
    return y;
}

__device__ __forceinline__ void mma_f16(float c[4], const uint32_t a[4], const uint32_t b[2]) {
    asm volatile("mma.sync.aligned.m16n8k16.row.col.f32.f16.f16.f32 "
        "{%0,%1,%2,%3}, {%4,%5,%6,%7}, {%8,%9}, {%0,%1,%2,%3};"
        : "+f"(c[0]), "+f"(c[1]), "+f"(c[2]), "+f"(c[3])
        : "r"(a[0]), "r"(a[1]), "r"(a[2]), "r"(a[3]), "r"(b[0]), "r"(b[1]));
}

__device__ __forceinline__ void ldmx4(uint32_t r[4], uint32_t addr) {
    asm volatile("ldmatrix.sync.aligned.m8n8.x4.shared.b16 {%0,%1,%2,%3}, [%4];"
        : "=r"(r[0]), "=r"(r[1]), "=r"(r[2]), "=r"(r[3]) : "r"(addr));
}
__device__ __forceinline__ void ldmx4t(uint32_t r[4], uint32_t addr) {
    asm volatile("ldmatrix.sync.aligned.m8n8.x4.trans.shared.b16 {%0,%1,%2,%3}, [%4];"
        : "=r"(r[0]), "=r"(r[1]), "=r"(r[2]), "=r"(r[3]) : "r"(addr));
}
__device__ __forceinline__ void ldmx2t(uint32_t r[2], uint32_t addr) {
    asm volatile("ldmatrix.sync.aligned.m8n8.x2.trans.shared.b16 {%0,%1}, [%2];"
        : "=r"(r[0]), "=r"(r[1]) : "r"(addr));
}

__device__ __forceinline__ void cp16(__half* s, const __half* g) {
    uint32_t sa = (uint32_t)__cvta_generic_to_shared(s);
    asm volatile("cp.async.cg.shared.global [%0], [%1], 16;" :: "r"(sa), "l"(g));
}
__device__ __forceinline__ void cp_commit() { asm volatile("cp.async.commit_group;"); }
__device__ __forceinline__ void cp_wait1()  { asm volatile("cp.async.wait_group 1;"); }
__device__ __forceinline__ void cp_wait0()  { asm volatile("cp.async.wait_group 0;"); }

// ---------------------------------------------------------------------------
// Pre-round: fp16-round x and all weight matrices into scratch (one-time)
// ---------------------------------------------------------------------------
#define NX4 (NROWS*NF/4)      // 2097152
#define NW4 (NHDK*NF/4)       // 65536

__global__ void preround_kernel(const float* __restrict__ x,
                                const float* __restrict__ wq,
                                const float* __restrict__ wk,
                                const float* __restrict__ wv,
                                const float* __restrict__ wo)
{
    int i4 = blockIdx.x * 256 + threadIdx.x;
    float4 v; __half* dst;
    if (i4 < NX4) {
        v = ((const float4*)x)[i4];
        dst = g_x + i4*4;
    } else {
        int j = i4 - NX4;
        int a = j >> 16;
        int off = j & 65535;
        const float* src = (a == 0) ? wq : (a == 1) ? wk : (a == 2) ? wv : wo;
        v = ((const float4*)src)[off];
        dst = ((a < 3) ? (g_wqkv + a*NHDK*NF) : g_wo) + off*4;
    }
    uint2 o;
    o.x = pack_h2(v.x, v.y);
    o.y = pack_h2(v.z, v.w);
    *(uint2*)dst = o;
}

// ---------------------------------------------------------------------------
// fp16 GEMM: CTA 64x128, warp tile 32x32, 3 CTAs/SM. XOR-swizzled 128B rows,
// 3-stage cp.async. Inner ks-steps software-pipelined: fragments of step k+1
// are loaded (LDSM) before the MMAs of step k, double-buffered in registers.
// ---------------------------------------------------------------------------
#define SST 64                    // halves per row
#define SSTAGE (192*SST)          // 12288 halves per stage

__device__ __forceinline__ void gemm_issue(const __half* __restrict__ A,
                                           const __half* __restrict__ W,
                                           __half* sg, int stage, int mBase, int nBase,
                                           int k0, int tid)
{
    __half* St = sg + stage*SSTAGE;
    #pragma unroll
    for (int it = 0; it < 6; ++it) {
        int c = tid + it*256;                 // 0..1535 16B-chunks
        int r = c >> 3, ck = c & 7;
        int sw = (ck ^ (r & 7)) << 3;         // swizzled halves offset in row
        const __half* src = (r < 64) ? (A + (mBase + r)*NF + k0 + ck*8)
                                     : (W + (nBase + (r - 64))*NF + k0 + ck*8);
        cp16(&St[r*SST + sw], src);
    }
    cp_commit();
}

__device__ __forceinline__ uint32_t sw_addr(uint32_t stbase, int r, int ck) {
    return stbase + (uint32_t)(r*128 + ((ck ^ (r & 7)) << 4));
}

__device__ __forceinline__ void gemm_frag_load(uint32_t st, int ar, int ac, int br, int bc,
                                               int ks, uint32_t af[2][4], uint32_t bf[2][4])
{
    #pragma unroll
    for (int im = 0; im < 2; ++im)
        ldmx4(af[im], sw_addr(st, ar + 16*im, 2*ks + ac));
    #pragma unroll
    for (int p = 0; p < 2; ++p)
        ldmx4(bf[p], sw_addr(st, br + 16*p, 2*ks + bc));
}

__device__ __forceinline__ void gemm_frag_mma(float acc[2][4][4],
                                              const uint32_t af[2][4], const uint32_t bf[2][4])
{
    #pragma unroll
    for (int p = 0; p < 2; ++p)
        #pragma unroll
        for (int im = 0; im < 2; ++im) {
            mma_f16(acc[im][2*p],   af[im], &bf[p][0]);
            mma_f16(acc[im][2*p+1], af[im], &bf[p][2]);
        }
}

__device__ __forceinline__ void gemm_mainloop(const __half* __restrict__ A,
                                              const __half* __restrict__ W,
                                              __half* sg, int mBase, int nBase,
                                              float acc[2][4][4], int tid)
{
    const int lane = tid & 31;
    const int wid = tid >> 5;
    const int wm = wid >> 2;          // 0..1
    const int wn = wid & 3;           // 0..3

    gemm_issue(A, W, sg, 0, mBase, nBase, 0, tid);
    gemm_issue(A, W, sg, 1, mBase, nBase, 64, tid);

    const uint32_t sbase = (uint32_t)__cvta_generic_to_shared(sg);
    const int ar = 32*wm + (lane & 15);
    const int ac = lane >> 4;                         // 0..1
    const int br = 64 + 32*wn + 8*((lane >> 4) & 1) + (lane & 7);
    const int bc = (lane >> 3) & 1;

    #pragma unroll
    for (int kk = 0; kk < 8; ++kk) {
        const int cur = kk % 3;
        if (kk < 7) cp_wait1(); else cp_wait0();   // exact: tile kk resident
        __syncthreads();
        if (kk + 2 < 8) gemm_issue(A, W, sg, (kk+2) % 3, mBase, nBase, (kk+2)*64, tid);

        const uint32_t st = sbase + (uint32_t)(cur*SSTAGE)*2u;

        // Software-pipelined ks-steps: LDSM(ks+1) issued before MMA(ks),
        // double-buffered fragments (fits the 85-reg budget at 3 CTAs/SM).
        uint32_t afA[2][4], bfA[2][4], afB[2][4], bfB[2][4];
        gemm_frag_load(st, ar, ac, br, bc, 0, afA, bfA);
        gemm_frag_load(st, ar, ac, br, bc, 1, afB, bfB);
        gemm_frag_mma(acc, afA, bfA);
        gemm_frag_load(st, ar, ac, br, bc, 2, afA, bfA);
        gemm_frag_mma(acc, afB, bfB);
        gemm_frag_load(st, ar, ac, br, bc, 3, afB, bfB);
        gemm_frag_mma(acc, afA, bfA);
        gemm_frag_mma(acc, afB, bfB);
    }
}

// ---------------------------------------------------------------------------
// QKV projection. Q gets the softmax scale (log2e/8) folded in at epilogue.
// ---------------------------------------------------------------------------
__global__ __launch_bounds__(256, 3)
void qkv_gemm_tc(const int* __restrict__ xlen,
                 const float* __restrict__ bq, const float* __restrict__ bk,
                 const float* __restrict__ bv)
{
    extern __shared__ __half sg[];
    const int mBase = blockIdx.x * 64;
    const int nBase = blockIdx.y * 128;
    const int z = blockIdx.z;

    const float* bias; __half* out;
    if (z == 0)      { bias = bq; out = g_q; }
    else if (z == 1) { bias = bk; out = g_k; }
    else             { bias = bv; out = g_v; }

    // Skip masked K/V rows (their softmax weights are exactly 0 downstream).
    if (z != 0) {
        const int bb = mBase >> 10;
        const int lim = xlen[bb] - 1;
        if (lim > 0 && (mBase & 1023) >= lim) return;
    }

    const int tid = threadIdx.x;
    const int lane = tid & 31;
    const int wid = tid >> 5;
    const int wm = wid >> 2, wn = wid & 3;
    const int g = lane >> 2, t = lane & 3;

    float acc[2][4][4];
    #pragma unroll
    for (int i = 0; i < 2; ++i)
        #pragma unroll
        for (int j = 0; j < 4; ++j)
            #pragma unroll
            for (int e = 0; e < 4; ++e) acc[i][j][e] = 0.f;

    gemm_mainloop(g_x, g_wqkv + z*NHDK*NF, sg, mBase, nBase, acc, tid);

    // Epilogue: fp16-round (acc+bias)[*QSCALE if Q] into [B,H,S,DK]
    const bool isQ = (z == 0);
    #pragma unroll
    for (int im = 0; im < 2; ++im) {
        int mlo = mBase + 32*wm + 16*im + g;
        int mhi = mlo + 8;
        int blo = mlo >> 10, slo = mlo & 1023;
        int bhi = mhi >> 10, shi = mhi & 1023;
        #pragma unroll
        for (int jn = 0; jn < 4; ++jn) {
            int n = nBase + 32*wn + 8*jn + 2*t;
            int h = n >> 6, d = n & 63;
            float v0 = acc[im][jn][0] + bias[n];
            float v1 = acc[im][jn][1] + bias[n+1];
            float v2 = acc[im][jn][2] + bias[n];
            float v3 = acc[im][jn][3] + bias[n+1];
            if (isQ) { v0 *= QSCALE; v1 *= QSCALE; v2 *= QSCALE; v3 *= QSCALE; }
            *(uint32_t*)(out + ((blo*NH + h)*NS + slo) * NDK + d) = pack_h2(v0, v1);
            *(uint32_t*)(out + ((bhi*NH + h)*NS + shi) * NDK + d) = pack_h2(v2, v3);
        }
    }
}

// ---------------------------------------------------------------------------
// Output projection (fp32 out)
// ---------------------------------------------------------------------------
__global__ __launch_bounds__(256, 3)
void out_gemm_tc(const float* __restrict__ WOb, float* __restrict__ outp)
{
    extern __shared__ __half sg[];
    const int mBase = blockIdx.x * 64;
    const int nBase = blockIdx.y * 128;

    const int tid = threadIdx.x;
    const int lane = tid & 31;
    const int wid = tid >> 5;
    const int wm = wid >> 2, wn = wid & 3;
    const int g = lane >> 2, t = lane & 3;

    float acc[2][4][4];
    #pragma unroll
    for (int i = 0; i < 2; ++i)
        #pragma unroll
        for (int j = 0; j < 4; ++j)
            #pragma unroll
            for (int e = 0; e < 4; ++e) acc[i][j][e] = 0.f;

    gemm_mainloop(g_z, g_wo, sg, mBase, nBase, acc, tid);

    #pragma unroll
    for (int im = 0; im < 2; ++im) {
        int mlo = mBase + 32*wm + 16*im + g;
        int mhi = mlo + 8;
        #pragma unroll
        for (int jn = 0; jn < 4; ++jn) {
            int n = nBase + 32*wn + 8*jn + 2*t;
            float bx = WOb[n], by = WOb[n+1];
            *(float2*)(outp + mlo * NF + n) = make_float2(acc[im][jn][0] + bx, acc[im][jn][1] + by);
            *(float2*)(outp + mhi * NF + n) = make_float2(acc[im][jn][2] + bx, acc[im][jn][3] + by);
        }
    }
}

// ---------------------------------------------------------------------------
// Flash attention, UNIFIED path (unchanged from round 16). 4-stage K/V ring,
// two tiles per barrier, exp2-domain scores, f16x2 ex2, tensor-pipe l via
// ones-column in the V pad. lim<=0 blocks reproduce the reference's fp32
// quantization via the (q - 999999) + 999999 cancellation transform.
// Grid: x = bh (wave mixing), y = qtile.
// ---------------------------------------------------------------------------
#define KVST 72                  // halves stride for K and V tiles
#define KVWORDS (64*KVST)        // 4608 halves per tile
// smem: K stages [4][4608] + V stages [4][4608] halves = 73728 B

__device__ __forceinline__ void attn_issueKV(const __half* __restrict__ Kt,
                                             const __half* __restrict__ Vt,
                                             __half* Kd, __half* Vd, int tid)
{
    #pragma unroll
    for (int it = 0; it < 2; ++it) {
        int c = tid + it*256;            // 0..511 chunks
        int r = c >> 3, col = (c & 7) << 3;
        cp16(&Kd[r*KVST + col], Kt + r*NDK + col);
        cp16(&Vd[r*KVST + col], Vt + r*NDK + col);
    }
    cp_commit();
}

__global__ __launch_bounds__(256, 2)
void attn_tc_kernel(const int* __restrict__ xlen)
{
    extern __shared__ __half sm[];

    const int tid = threadIdx.x;
    const int w = tid >> 5;
    const int lane = tid & 31;
    const int g = lane >> 2, t = lane & 3;

    const int bh = blockIdx.x;           // bh-major block order: wave mixing
    const int qt = blockIdx.y;
    const int b = bh >> 3;
    const int h = bh & 7;
    const __half* Q = g_q + bh * NS * NDK + qt * 128 * NDK;
    const __half* K = g_k + bh * NS * NDK;
    const __half* V = g_v + bh * NS * NDK;
    const int lim = xlen[b] - 1;
    const bool legacy = (lim <= 0);
    const int nkt = legacy ? (NS/64) : min(NS/64, (lim + 63) >> 6);

    // Prologue: prefetch tiles 0,1 into stages 0,1 (one commit group per tile)
    attn_issueKV(K, V, sm, sm + 4*KVWORDS, tid);
    if (nkt > 1) attn_issueKV(K + 64*NDK, V + 64*NDK, sm + KVWORDS, sm + 5*KVWORDS, tid);

    // Ones-column pad init for all 4 V stages: row pad = [1.0, 0 x7] halves.
    {
        int i = tid;                     // 4*64 = 256 rows, one per thread
        uint4 pad = make_uint4(0x00003C00u, 0u, 0u, 0u);
        *(uint4*)&sm[(4 + (i >> 6))*KVWORDS + (i & 63)*KVST + 64] = pad;
    }

    // Q fragments straight from gmem (pre-rounded + pre-scaled fp16)
    uint32_t qa[4][4];
    {
        const __half* Qr0 = Q + (16*w + g) * NDK;
        const __half* Qr1 = Qr0 + 8 * NDK;
        #pragma unroll
        for (int jd = 0; jd < 4; ++jd) {
            qa[jd][0] = *(const uint32_t*)(Qr0 + 16*jd + 2*t);
            qa[jd][1] = *(const uint32_t*)(Qr1 + 16*jd + 2*t);
            qa[jd][2] = *(const uint32_t*)(Qr0 + 16*jd + 2*t + 8);
            qa[jd][3] = *(const uint32_t*)(Qr1 + 16*jd + 2*t + 8);
        }
    }

    float o[8][4];
    #pragma unroll
    for (int nf = 0; nf < 8; ++nf)
        #pragma unroll
        for (int e = 0; e < 4; ++e) o[nf][e] = 0.f;
    float ol[4] = {0.f, 0.f, 0.f, 0.f};   // row-sum accumulator (ones column)

    const uint32_t sbase = (uint32_t)__cvta_generic_to_shared(sm);
    const int krow = 8*((lane >> 4) & 1) + (lane & 7);
    const int kcol = ((lane >> 3) & 1) << 3;
    const int vrow = lane & 15;
    const int vcol = ((lane >> 4) & 1) << 3;

    auto process_tile = [&](int kt) {
        const uint32_t kS = sbase + (uint32_t)((kt & 3)*KVWORDS)*2u;
        const uint32_t vS = sbase + (uint32_t)((4 + (kt & 3))*KVWORDS)*2u;

        float sc[8][4];
        #pragma unroll
        for (int nf = 0; nf < 8; ++nf)
            #pragma unroll
            for (int e = 0; e < 4; ++e) sc[nf][e] = 0.f;

        #pragma unroll
        for (int jd = 0; jd < 4; ++jd) {
            #pragma unroll
            for (int p = 0; p < 4; ++p) {          // key-block pairs
                uint32_t kb[4];
                ldmx4(kb, kS + (uint32_t)(((16*p + krow)*KVST + 16*jd + kcol) * 2));
                mma_f16(sc[2*p],   qa[jd], &kb[0]);
                mma_f16(sc[2*p+1], qa[jd], &kb[2]);
            }
        }

        const int kb0 = kt * 64;
        if (legacy) {
            #pragma unroll
            for (int nf = 0; nf < 8; ++nf)
                #pragma unroll
                for (int e = 0; e < 4; ++e) {
                    float q = sc[nf][e]*LN2F + (-999999.0f);   // fp32-quantized
                    sc[nf][e] = (q + 999999.0f) * LOG2EF;
                }
        } else if (kb0 + 64 > lim) {               // edge tile only: mask
            #pragma unroll
            for (int nf = 0; nf < 8; ++nf) {
                int key = kb0 + 8*nf + 2*t;
                if (key     >= lim) { sc[nf][0] += MASKL2; sc[nf][2] += MASKL2; }
                if (key + 1 >= lim) { sc[nf][1] += MASKL2; sc[nf][3] += MASKL2; }
            }
        }

        uint32_t ph[8][2];
        #pragma unroll
        for (int nf = 0; nf < 8; ++nf) {
            ph[nf][0] = ex2_h2(pack_h2(sc[nf][0], sc[nf][1]));
            ph[nf][1] = ex2_h2(pack_h2(sc[nf][2], sc[nf][3]));
        }
        #pragma unroll
        for (int j = 0; j < 4; ++j) {
            uint32_t pa[4];
            pa[0] = ph[2*j][0];   pa[1] = ph[2*j][1];
            pa[2] = ph[2*j+1][0]; pa[3] = ph[2*j+1][1];
            #pragma unroll
            for (int p = 0; p < 4; ++p) {          // d-block pairs
                uint32_t vb[4];
                ldmx4t(vb, vS + (uint32_t)(((16*j + vrow)*KVST + 16*p + vcol) * 2));
                mma_f16(o[2*p],   pa, &vb[0]);
                mma_f16(o[2*p+1], pa, &vb[2]);
            }
            uint32_t vl[2];
            ldmx2t(vl, vS + (uint32_t)(((16*j + vrow)*KVST + 64) * 2));
            mma_f16(ol, pa, vl);
        }
    };

    // Pair loop: one wait+barrier per TWO tiles.
    for (int kt0 = 0; kt0 < nkt; kt0 += 2) {
        cp_wait0();          // tiles kt0, kt0+1 resident (issued >= 1 pair ago)
        __syncthreads();     // visibility + stage-reuse protection (1-iter lag)
        if (kt0 + 2 < nkt)
            attn_issueKV(K + (kt0+2)*64*NDK, V + (kt0+2)*64*NDK,
                         sm + ((kt0+2)&3)*KVWORDS, sm + (4 + ((kt0+2)&3))*KVWORDS, tid);
        if (kt0 + 3 < nkt)
            attn_issueKV(K + (kt0+3)*64*NDK, V + (kt0+3)*64*NDK,
                         sm + ((kt0+3)&3)*KVWORDS, sm + (4 + ((kt0+3)&3))*KVWORDS, tid);

        process_tile(kt0);
        if (kt0 + 1 < nkt) process_tile(kt0 + 1);
    }

    // l extraction: ones column lives in c[0]/c[2] of t==0 lanes; broadcast.
    const int src = lane & ~3;
    const float l0 = __shfl_sync(0xffffffffu, ol[0], src);
    const float l1 = __shfl_sync(0xffffffffu, ol[2], src);

    // Epilogue: normalize, fp16-round, write g_z [B,S,H*DK]
    const float inv0 = 1.0f / l0, inv1 = 1.0f / l1;
    const int slo = qt * 128 + 16*w + g;
    const int shi = slo + 8;
    __half* zlo = g_z + (b*NS + slo) * NHDK + h * NDK;
    __half* zhi = g_z + (b*NS + shi) * NHDK + h * NDK;
    #pragma unroll
    for (int nf = 0; nf < 8; ++nf) {
        int d = 8*nf + 2*t;
        *(uint32_t*)(zlo + d) = pack_h2(o[nf][0] * inv0, o[nf][1] * inv0);
        *(uint32_t*)(zhi + d) = pack_h2(o[nf][2] * inv1, o[nf][3] * inv1);
    }
}

// ---------------------------------------------------------------------------

extern "C" void kernel_launch(void* const* d_in, const int* in_sizes, int n_in,
                              void* d_out, int out_size)
{
    (void)in_sizes; (void)n_in; (void)out_size;
    const float* x    = (const float*)d_in[0];
    const int*   xlen = (const int*)  d_in[1];
    const float* WQw  = (const float*)d_in[2];
    const float* WQb  = (const float*)d_in[3];
    const float* WKw  = (const float*)d_in[4];
    const float* WKb  = (const float*)d_in[5];
    const float* WVw  = (const float*)d_in[6];
    const float* WVb  = (const float*)d_in[7];
    const float* WOw  = (const float*)d_in[8];
    const float* WOb  = (const float*)d_in[9];
    float* outp = (float*)d_out;

    const int gemm_smem = 3 * SSTAGE * (int)sizeof(__half);     // 73728
    const int attn_smem = 8 * KVWORDS * (int)sizeof(__half);    // 73728
    cudaFuncSetAttribute(qkv_gemm_tc, cudaFuncAttributeMaxDynamicSharedMemorySize, gemm_smem);
    cudaFuncSetAttribute(out_gemm_tc, cudaFuncAttributeMaxDynamicSharedMemorySize, gemm_smem);
    cudaFuncSetAttribute(attn_tc_kernel, cudaFuncAttributeMaxDynamicSharedMemorySize, attn_smem);

    preround_kernel<<<(NX4 + 4*NW4) / 256, 256>>>(x, WQw, WKw, WVw, WOw);
    qkv_gemm_tc<<<dim3(NROWS/64, NHDK/128, 3), 256, gemm_smem>>>(xlen, WQb, WKb, WVb);
    attn_tc_kernel<<<dim3(NB*NH, NS/128), 256, attn_smem>>>(xlen);
    out_gemm_tc<<<dim3(NROWS/64, NF/128), 256, gemm_smem>>>(WOb, outp);
}